// round 3
// baseline (speedup 1.0000x reference)
#include <cuda_runtime.h>
#include <math.h>

#define DIM   512
#define N_ELEM (DIM*DIM)       // 262144
#define KFLAT 1024             // DT*2

// ---------------- device state ----------------
__device__ float g_A[N_ELEM];        // y
__device__ float g_f[N_ELEM];        // fy (FSAL, = k1)
__device__ float g_ynew[N_ELEM];
__device__ float g_k2[N_ELEM];
__device__ float g_k3[N_ELEM];
__device__ float g_k4[N_ELEM];
__device__ float g_k5[N_ELEM];
__device__ float g_k6[N_ELEM];
__device__ float g_k7[N_ELEM];
__device__ float g_basis[N_ELEM*2];  // [b, j*2+k] interleaved sin/cos
__device__ float g_red[1024];
// ctl: 0=t, 1=h, 2=hs, 5=h0, 6=d1
__device__ float g_ctl[8];
__device__ int   g_done;
__device__ int   g_accept;

// stage coefficient tables (Dormand-Prince)
__constant__ float STG_C[8][6] = {
  {0.f,0.f,0.f,0.f,0.f,0.f},                                            // 0: f0
  {1.f,0.f,0.f,0.f,0.f,0.f},                                            // 1: f1 init
  {0.2f,0.f,0.f,0.f,0.f,0.f},                                           // 2: k2
  {3.f/40.f, 9.f/40.f, 0.f,0.f,0.f,0.f},                                // 3: k3
  {44.f/45.f, -56.f/15.f, 32.f/9.f, 0.f,0.f,0.f},                       // 4: k4
  {19372.f/6561.f, -25360.f/2187.f, 64448.f/6561.f, -212.f/729.f,0.f,0.f}, // 5: k5
  {9017.f/3168.f, -355.f/33.f, 46732.f/5247.f, 49.f/176.f, -5103.f/18656.f, 0.f}, // 6: k6
  {35.f/384.f, 0.f, 500.f/1113.f, 125.f/192.f, -2187.f/6784.f, 11.f/84.f},       // 7: ynew
};
__constant__ float STG_T[8] = {0.f, 1.f, 0.2f, 0.3f, 0.8f, 8.f/9.f, 1.f, 1.f};

__constant__ float ERR_C[6] = { 71.f/57600.f, -71.f/16695.f, 71.f/1920.f,
                                -17253.f/339200.f, 22.f/525.f, -1.f/40.f };

// ---------------- control kernels ----------------
__global__ void k_init_ctl() {
  g_done = 0; g_accept = 0; g_ctl[0] = 0.f;
}

__global__ void k_begin() {
  if (g_done) return;
  g_ctl[2] = fminf(g_ctl[1], 1.0f - g_ctl[0]);
}

// ---------------- elementwise stage: ytmp + basis ----------------
__global__ __launch_bounds__(256) void k_stage(int sid, int nK, int writeYnew, int checkDone) {
  if (checkDone && g_done) return;
  const float* karr[6] = {g_f, g_k2, g_k3, g_k4, g_k5, g_k6};
  float hs = g_ctl[2];
  float ts = g_ctl[0] + STG_T[sid] * hs;
  int base = blockIdx.x * 512 + threadIdx.x;
  #pragma unroll
  for (int r = 0; r < 2; r++) {
    int i = base + r * 256;
    float y = g_A[i];
    float yt = y;
    if (nK > 0) {
      float acc = 0.f;
      for (int j = 0; j < nK; j++) acc += STG_C[sid][j] * karr[j][i];
      yt = y + hs * acc;
    }
    if (writeYnew) g_ynew[i] = yt;
    float ph = yt + ts;      // TA=1, TB=1, TC=0
    float s, c;
    sincosf(ph, &s, &c);
    g_basis[2*i]   = s;
    g_basis[2*i+1] = c;
  }
}

// ---------------- GEMM: out = basis[512,1024] * Cflat[512,1024]^T ----------------
__global__ __launch_bounds__(256) void k_gemm_nt(const float* __restrict__ Bm, int dstId, int checkDone) {
  if (checkDone && g_done) return;
  float* dsts[7] = {g_f, g_k2, g_k3, g_k4, g_k5, g_k6, g_k7};
  float* D = dsts[dstId];
  const float* A = g_basis;
  __shared__ float As[16][64];
  __shared__ float Bs[16][64];
  int tid = threadIdx.x;
  int tx = tid & 15, ty = tid >> 4;
  int row0 = blockIdx.y * 64, col0 = blockIdx.x * 64;
  int lr = tid >> 2;
  int lc = (tid & 3) * 4;
  float acc[4][4] = {};
  for (int k0 = 0; k0 < KFLAT; k0 += 16) {
    float4 av = *(const float4*)&A [(row0 + lr) * KFLAT + k0 + lc];
    float4 bv = *(const float4*)&Bm[(col0 + lr) * KFLAT + k0 + lc];
    As[lc+0][lr]=av.x; As[lc+1][lr]=av.y; As[lc+2][lr]=av.z; As[lc+3][lr]=av.w;
    Bs[lc+0][lr]=bv.x; Bs[lc+1][lr]=bv.y; Bs[lc+2][lr]=bv.z; Bs[lc+3][lr]=bv.w;
    __syncthreads();
    #pragma unroll
    for (int kk = 0; kk < 16; kk++) {
      float4 a = *(const float4*)&As[kk][ty*4];
      float4 b = *(const float4*)&Bs[kk][tx*4];
      float ar[4] = {a.x,a.y,a.z,a.w};
      float br[4] = {b.x,b.y,b.z,b.w};
      #pragma unroll
      for (int i = 0; i < 4; i++)
        #pragma unroll
        for (int j = 0; j < 4; j++)
          acc[i][j] += ar[i] * br[j];
    }
    __syncthreads();
  }
  #pragma unroll
  for (int i = 0; i < 4; i++) {
    float4 o = {acc[i][0], acc[i][1], acc[i][2], acc[i][3]};
    *(float4*)&D[(row0 + ty*4 + i) * DIM + col0 + tx*4] = o;
  }
}

// ---------------- GEMM NN: mode 0: g_A = x*P ; mode 1: out = g_A*F ----------------
__global__ __launch_bounds__(256) void k_gemm_nn(const float* __restrict__ Aext,
                                                const float* __restrict__ Bm,
                                                float* outExt, int mode) {
  const float* A = mode ? g_A : Aext;
  float* D = mode ? outExt : g_A;
  const int K = DIM;
  __shared__ float As[16][64];
  __shared__ float Bs[16][64];
  int tid = threadIdx.x;
  int tx = tid & 15, ty = tid >> 4;
  int row0 = blockIdx.y * 64, col0 = blockIdx.x * 64;
  int lr = tid >> 2;          // A-load row 0..63
  int lc = (tid & 3) * 4;     // A-load k 0,4,8,12
  int br = tid >> 4;          // B-load k 0..15
  int bc = (tid & 15) * 4;    // B-load col
  float acc[4][4] = {};
  for (int k0 = 0; k0 < K; k0 += 16) {
    float4 av = *(const float4*)&A[(row0 + lr) * K + k0 + lc];
    As[lc+0][lr]=av.x; As[lc+1][lr]=av.y; As[lc+2][lr]=av.z; As[lc+3][lr]=av.w;
    float4 bv = *(const float4*)&Bm[(k0 + br) * DIM + col0 + bc];
    *(float4*)&Bs[br][bc] = bv;
    __syncthreads();
    #pragma unroll
    for (int kk = 0; kk < 16; kk++) {
      float4 a = *(const float4*)&As[kk][ty*4];
      float4 b = *(const float4*)&Bs[kk][tx*4];
      float ar[4] = {a.x,a.y,a.z,a.w};
      float br2[4] = {b.x,b.y,b.z,b.w};
      #pragma unroll
      for (int i = 0; i < 4; i++)
        #pragma unroll
        for (int j = 0; j < 4; j++)
          acc[i][j] += ar[i] * br2[j];
    }
    __syncthreads();
  }
  #pragma unroll
  for (int i = 0; i < 4; i++) {
    float4 o = {acc[i][0], acc[i][1], acc[i][2], acc[i][3]};
    *(float4*)&D[(row0 + ty*4 + i) * DIM + col0 + tx*4] = o;
  }
}

// ---------------- reductions ----------------
__device__ __forceinline__ float blockReduce(float v, float* sh) {
  int tid = threadIdx.x;
  sh[tid] = v; __syncthreads();
  for (int s = 128; s > 0; s >>= 1) {
    if (tid < s) sh[tid] += sh[tid + s];
    __syncthreads();
  }
  return sh[0];
}

__global__ __launch_bounds__(256) void k_red_init0() {
  __shared__ float sh[256];
  int base = blockIdx.x * 512 + threadIdx.x;
  float s0 = 0.f, s1 = 0.f;
  #pragma unroll
  for (int r = 0; r < 2; r++) {
    int i = base + r * 256;
    float y = g_A[i], f = g_f[i];
    float sc = 1e-6f + 1e-3f * fabsf(y);
    float a = y / sc, b = f / sc;
    s0 += a * a; s1 += b * b;
  }
  float S0 = blockReduce(s0, sh);
  __syncthreads();
  float S1 = blockReduce(s1, sh);
  if (threadIdx.x == 0) { g_red[blockIdx.x] = S0; g_red[512 + blockIdx.x] = S1; }
}

__global__ __launch_bounds__(256) void k_fin0() {
  __shared__ float sh[256];
  int tid = threadIdx.x;
  float S0 = blockReduce(g_red[tid] + g_red[tid + 256], sh);
  __syncthreads();
  float S1 = blockReduce(g_red[512 + tid] + g_red[768 + tid], sh);
  if (tid == 0) {
    float d0 = sqrtf(S0 / (float)N_ELEM);
    float d1 = sqrtf(S1 / (float)N_ELEM);
    float h0 = (d0 < 1e-5f || d1 < 1e-5f) ? 1e-6f : 0.01f * d0 / d1;
    g_ctl[0] = 0.f; g_ctl[2] = h0; g_ctl[5] = h0; g_ctl[6] = d1;
  }
}

__global__ __launch_bounds__(256) void k_red_init1() {
  __shared__ float sh[256];
  int base = blockIdx.x * 512 + threadIdx.x;
  float s = 0.f;
  #pragma unroll
  for (int r = 0; r < 2; r++) {
    int i = base + r * 256;
    float y = g_A[i];
    float sc = 1e-6f + 1e-3f * fabsf(y);
    float d = (g_k2[i] - g_f[i]) / sc;     // f1 lives in g_k2
    s += d * d;
  }
  float S = blockReduce(s, sh);
  if (threadIdx.x == 0) g_red[blockIdx.x] = S;
}

__global__ __launch_bounds__(256) void k_fin1() {
  __shared__ float sh[256];
  int tid = threadIdx.x;
  float S = blockReduce(g_red[tid] + g_red[tid + 256], sh);
  if (tid == 0) {
    float h0 = g_ctl[5];
    float d2 = sqrtf(S / (float)N_ELEM) / h0;
    float d1 = g_ctl[6];
    float dmax = fmaxf(d1, d2);
    float h1 = (dmax <= 1e-15f) ? fmaxf(1e-6f, h0 * 1e-3f)
                                : powf(0.01f / dmax, 0.2f);
    g_ctl[1] = fminf(fminf(100.f * h0, h1), 1.0f);
    g_ctl[0] = 0.f;
  }
}

__global__ __launch_bounds__(256) void k_err_red() {
  if (g_done) return;
  __shared__ float sh[256];
  float hs = g_ctl[2];
  int base = blockIdx.x * 512 + threadIdx.x;
  float s = 0.f;
  #pragma unroll
  for (int r = 0; r < 2; r++) {
    int i = base + r * 256;
    float e = ERR_C[0]*g_f[i] + ERR_C[1]*g_k3[i] + ERR_C[2]*g_k4[i]
            + ERR_C[3]*g_k5[i] + ERR_C[4]*g_k6[i] + ERR_C[5]*g_k7[i];
    e *= hs;
    float y = g_A[i], yn = g_ynew[i];
    float sc = 1e-6f + 1e-3f * fmaxf(fabsf(y), fabsf(yn));
    float d = e / sc;
    s += d * d;
  }
  float S = blockReduce(s, sh);
  if (threadIdx.x == 0) g_red[blockIdx.x] = S;
}

__global__ __launch_bounds__(256) void k_finalize() {
  if (g_done) { if (threadIdx.x == 0) g_accept = 0; return; }
  __shared__ float sh[256];
  int tid = threadIdx.x;
  float S = blockReduce(g_red[tid] + g_red[tid + 256], sh);
  if (tid == 0) {
    float en = sqrtf(S / (float)N_ELEM);
    int accept = en < 1.0f;
    float safe = fmaxf(en, 1e-10f);
    float p = 0.9f * powf(safe, -0.2f);
    float fac = accept ? fminf(10.f, p) : fmaxf(0.2f, p);
    float hs = g_ctl[2];
    if (accept) g_ctl[0] = g_ctl[0] + hs;
    g_ctl[1] = hs * fac;
    g_accept = accept;
    if (g_ctl[0] >= 1.0f - 1e-7f) g_done = 1;
  }
}

__global__ __launch_bounds__(256) void k_commit() {
  if (!g_accept) return;
  int base = blockIdx.x * 512 + threadIdx.x;
  #pragma unroll
  for (int r = 0; r < 2; r++) {
    int i = base + r * 256;
    g_A[i] = g_ynew[i];
    g_f[i] = g_k7[i];
  }
}

// ---------------- host launcher ----------------
extern "C" void kernel_launch(void* const* d_in, const int* in_sizes, int n_in,
                              void* d_out, int out_size) {
  const float* x = (const float*)d_in[0];
  const float* P = (const float*)d_in[1];
  const float* C = (const float*)d_in[2];
  const float* F = (const float*)d_in[3];
  float* out = (float*)d_out;

  dim3 g88(8, 8);
  const int EB = 512, ET = 256;

  k_init_ctl<<<1, 1>>>();
  // A0 = x @ P
  k_gemm_nn<<<g88, 256>>>(x, P, nullptr, 0);
  // f0 = f(0, A0)
  k_stage<<<EB, ET>>>(0, 0, 0, 0);
  k_gemm_nt<<<g88, 256>>>(C, 0, 0);
  // initial step size selection
  k_red_init0<<<EB, ET>>>();
  k_fin0<<<1, 256>>>();
  k_stage<<<EB, ET>>>(1, 1, 0, 0);      // ytmp = y0 + h0*f0 at t=h0
  k_gemm_nt<<<g88, 256>>>(C, 1, 0);     // f1 -> g_k2
  k_red_init1<<<EB, ET>>>();
  k_fin1<<<1, 256>>>();

  for (int s = 0; s < 20; s++) {
    k_begin<<<1, 1>>>();
    k_stage<<<EB, ET>>>(2, 1, 0, 1); k_gemm_nt<<<g88, 256>>>(C, 1, 1);  // k2
    k_stage<<<EB, ET>>>(3, 2, 0, 1); k_gemm_nt<<<g88, 256>>>(C, 2, 1);  // k3
    k_stage<<<EB, ET>>>(4, 3, 0, 1); k_gemm_nt<<<g88, 256>>>(C, 3, 1);  // k4
    k_stage<<<EB, ET>>>(5, 4, 0, 1); k_gemm_nt<<<g88, 256>>>(C, 4, 1);  // k5
    k_stage<<<EB, ET>>>(6, 5, 0, 1); k_gemm_nt<<<g88, 256>>>(C, 5, 1);  // k6
    k_stage<<<EB, ET>>>(7, 6, 1, 1); k_gemm_nt<<<g88, 256>>>(C, 6, 1);  // ynew + k7
    k_err_red<<<EB, ET>>>();
    k_finalize<<<1, 256>>>();
    k_commit<<<EB, ET>>>();
  }

  // y_hat = A_f @ F
  k_gemm_nn<<<g88, 256>>>(nullptr, F, out, 1);
}

// round 5
// speedup vs baseline: 1.6036x; 1.6036x over previous
#include <cuda_runtime.h>
#include <math.h>

#define DIM   512
#define N_ELEM (DIM*DIM)       // 262144
#define KFLAT 1024             // DT*2

// ---------------- device state ----------------
__device__ float g_A[N_ELEM];                // y
__device__ float g_K[7][2][N_ELEM];          // k1..k7, split-K partials
__device__ float g_ynew[N_ELEM];
__device__ float g_basis[N_ELEM*2];          // [b, j*2+k] interleaved sin/cos
__device__ float g_red[1024];
// ctl: 0=t, 1=h, 2=hs, 5=h0, 6=d1
__device__ float g_ctl[8];
__device__ int   g_done;
__device__ int   g_accept;

// stage coefficient tables (Dormand-Prince)
__constant__ float STG_C[8][6] = {
  {0.f,0.f,0.f,0.f,0.f,0.f},                                            // 0: f0
  {1.f,0.f,0.f,0.f,0.f,0.f},                                            // 1: f1 init
  {0.2f,0.f,0.f,0.f,0.f,0.f},                                           // 2: k2
  {3.f/40.f, 9.f/40.f, 0.f,0.f,0.f,0.f},                                // 3: k3
  {44.f/45.f, -56.f/15.f, 32.f/9.f, 0.f,0.f,0.f},                       // 4: k4
  {19372.f/6561.f, -25360.f/2187.f, 64448.f/6561.f, -212.f/729.f,0.f,0.f}, // 5: k5
  {9017.f/3168.f, -355.f/33.f, 46732.f/5247.f, 49.f/176.f, -5103.f/18656.f, 0.f}, // 6: k6
  {35.f/384.f, 0.f, 500.f/1113.f, 125.f/192.f, -2187.f/6784.f, 11.f/84.f},       // 7: ynew
};
__constant__ float STG_T[8] = {0.f, 1.f, 0.2f, 0.3f, 0.8f, 8.f/9.f, 1.f, 1.f};

__constant__ float ERR_C[6] = { 71.f/57600.f, -71.f/16695.f, 71.f/1920.f,
                                -17253.f/339200.f, 22.f/525.f, -1.f/40.f };
// ERR uses k1,k3,k4,k5,k6,k7 -> g_K indices 0,2,3,4,5,6
__constant__ int ERR_IDX[6] = {0, 2, 3, 4, 5, 6};

// ---------------- control kernels ----------------
__global__ void k_init_ctl() {
  g_done = 0; g_accept = 0; g_ctl[0] = 0.f;
}

__global__ void k_begin() {
  if (g_done) return;
  g_ctl[2] = fminf(g_ctl[1], 1.0f - g_ctl[0]);
}

// ---------------- elementwise stage: ytmp + basis ----------------
__global__ __launch_bounds__(256) void k_stage(int sid, int nK, int writeYnew, int checkDone) {
  if (checkDone && g_done) return;
  float hs = g_ctl[2];
  float ts = g_ctl[0] + STG_T[sid] * hs;
  int base = blockIdx.x * 512 + threadIdx.x;
  #pragma unroll
  for (int r = 0; r < 2; r++) {
    int i = base + r * 256;
    float y = g_A[i];
    float yt = y;
    if (nK > 0) {
      float acc = 0.f;
      for (int j = 0; j < nK; j++)
        acc += STG_C[sid][j] * (g_K[j][0][i] + g_K[j][1][i]);
      yt = y + hs * acc;
    }
    if (writeYnew) g_ynew[i] = yt;
    float ph = yt + ts;      // TA=1, TB=1, TC=0
    float s, c;
    sincosf(ph, &s, &c);
    g_basis[2*i]   = s;
    g_basis[2*i+1] = c;
  }
}

// ---------------- GEMM NT, split-K=2, double-buffered ----------------
// D_partial[z] = basis[512, z*512 : z*512+512] * Cflat[:, same]^T
__global__ __launch_bounds__(256) void k_gemm_nt(const float* __restrict__ Bm, int dstId, int checkDone) {
  if (checkDone && g_done) return;
  float* D = &g_K[dstId][blockIdx.z][0];
  const float* A = g_basis;
  __shared__ float As[2][16][64];
  __shared__ float Bs[2][16][64];
  int tid = threadIdx.x;
  int tx = tid & 15, ty = tid >> 4;
  int row0 = blockIdx.y * 64, col0 = blockIdx.x * 64;
  int lr = tid >> 2;          // 0..63
  int lc = (tid & 3) * 4;     // 0,4,8,12
  int kbase = blockIdx.z * 512;
  const float* Arow = &A [(row0 + lr) * KFLAT + kbase + lc];
  const float* Brow = &Bm[(col0 + lr) * KFLAT + kbase + lc];

  float acc[4][4] = {};
  // prologue: tile 0 -> buffer 0
  {
    float4 av = *(const float4*)Arow;
    float4 bv = *(const float4*)Brow;
    As[0][lc+0][lr]=av.x; As[0][lc+1][lr]=av.y; As[0][lc+2][lr]=av.z; As[0][lc+3][lr]=av.w;
    Bs[0][lc+0][lr]=bv.x; Bs[0][lc+1][lr]=bv.y; Bs[0][lc+2][lr]=bv.z; Bs[0][lc+3][lr]=bv.w;
  }
  __syncthreads();

  int cur = 0;
  for (int it = 0; it < 32; it++) {
    float4 av2, bv2;
    if (it < 31) {
      av2 = *(const float4*)(Arow + (it + 1) * 16);
      bv2 = *(const float4*)(Brow + (it + 1) * 16);
    }
    #pragma unroll
    for (int kk = 0; kk < 16; kk++) {
      float4 a = *(const float4*)&As[cur][kk][ty*4];
      float4 b = *(const float4*)&Bs[cur][kk][tx*4];
      float ar[4] = {a.x,a.y,a.z,a.w};
      float br[4] = {b.x,b.y,b.z,b.w};
      #pragma unroll
      for (int i = 0; i < 4; i++)
        #pragma unroll
        for (int j = 0; j < 4; j++)
          acc[i][j] += ar[i] * br[j];
    }
    if (it < 31) {
      int nxt = cur ^ 1;
      As[nxt][lc+0][lr]=av2.x; As[nxt][lc+1][lr]=av2.y; As[nxt][lc+2][lr]=av2.z; As[nxt][lc+3][lr]=av2.w;
      Bs[nxt][lc+0][lr]=bv2.x; Bs[nxt][lc+1][lr]=bv2.y; Bs[nxt][lc+2][lr]=bv2.z; Bs[nxt][lc+3][lr]=bv2.w;
      __syncthreads();
      cur = nxt;
    }
  }
  #pragma unroll
  for (int i = 0; i < 4; i++) {
    float4 o = {acc[i][0], acc[i][1], acc[i][2], acc[i][3]};
    *(float4*)&D[(row0 + ty*4 + i) * DIM + col0 + tx*4] = o;
  }
}

// ---------------- GEMM NN: mode 0: g_A = x*P ; mode 1: out = g_A*F ----------------
__global__ __launch_bounds__(256) void k_gemm_nn(const float* __restrict__ Aext,
                                                const float* __restrict__ Bm,
                                                float* outExt, int mode) {
  const float* A = mode ? g_A : Aext;
  float* D = mode ? outExt : g_A;
  const int K = DIM;
  __shared__ float As[16][64];
  __shared__ float Bs[16][64];
  int tid = threadIdx.x;
  int tx = tid & 15, ty = tid >> 4;
  int row0 = blockIdx.y * 64, col0 = blockIdx.x * 64;
  int lr = tid >> 2;
  int lc = (tid & 3) * 4;
  int br = tid >> 4;
  int bc = (tid & 15) * 4;
  float acc[4][4] = {};
  for (int k0 = 0; k0 < K; k0 += 16) {
    float4 av = *(const float4*)&A[(row0 + lr) * K + k0 + lc];
    As[lc+0][lr]=av.x; As[lc+1][lr]=av.y; As[lc+2][lr]=av.z; As[lc+3][lr]=av.w;
    float4 bv = *(const float4*)&Bm[(k0 + br) * DIM + col0 + bc];
    *(float4*)&Bs[br][bc] = bv;
    __syncthreads();
    #pragma unroll
    for (int kk = 0; kk < 16; kk++) {
      float4 a = *(const float4*)&As[kk][ty*4];
      float4 b = *(const float4*)&Bs[kk][tx*4];
      float ar[4] = {a.x,a.y,a.z,a.w};
      float br2[4] = {b.x,b.y,b.z,b.w};
      #pragma unroll
      for (int i = 0; i < 4; i++)
        #pragma unroll
        for (int j = 0; j < 4; j++)
          acc[i][j] += ar[i] * br2[j];
    }
    __syncthreads();
  }
  #pragma unroll
  for (int i = 0; i < 4; i++) {
    float4 o = {acc[i][0], acc[i][1], acc[i][2], acc[i][3]};
    *(float4*)&D[(row0 + ty*4 + i) * DIM + col0 + tx*4] = o;
  }
}

// ---------------- reductions ----------------
__device__ __forceinline__ float blockReduce(float v, float* sh) {
  int tid = threadIdx.x;
  sh[tid] = v; __syncthreads();
  for (int s = 128; s > 0; s >>= 1) {
    if (tid < s) sh[tid] += sh[tid + s];
    __syncthreads();
  }
  return sh[0];
}

__global__ __launch_bounds__(256) void k_red_init0() {
  __shared__ float sh[256];
  int base = blockIdx.x * 512 + threadIdx.x;
  float s0 = 0.f, s1 = 0.f;
  #pragma unroll
  for (int r = 0; r < 2; r++) {
    int i = base + r * 256;
    float y = g_A[i];
    float f = g_K[0][0][i] + g_K[0][1][i];
    float sc = 1e-6f + 1e-3f * fabsf(y);
    float a = y / sc, b = f / sc;
    s0 += a * a; s1 += b * b;
  }
  float S0 = blockReduce(s0, sh);
  __syncthreads();
  float S1 = blockReduce(s1, sh);
  if (threadIdx.x == 0) { g_red[blockIdx.x] = S0; g_red[512 + blockIdx.x] = S1; }
}

__global__ __launch_bounds__(256) void k_fin0() {
  __shared__ float sh[256];
  int tid = threadIdx.x;
  float S0 = blockReduce(g_red[tid] + g_red[tid + 256], sh);
  __syncthreads();
  float S1 = blockReduce(g_red[512 + tid] + g_red[768 + tid], sh);
  if (tid == 0) {
    float d0 = sqrtf(S0 / (float)N_ELEM);
    float d1 = sqrtf(S1 / (float)N_ELEM);
    float h0 = (d0 < 1e-5f || d1 < 1e-5f) ? 1e-6f : 0.01f * d0 / d1;
    g_ctl[0] = 0.f; g_ctl[2] = h0; g_ctl[5] = h0; g_ctl[6] = d1;
  }
}

__global__ __launch_bounds__(256) void k_red_init1() {
  __shared__ float sh[256];
  int base = blockIdx.x * 512 + threadIdx.x;
  float s = 0.f;
  #pragma unroll
  for (int r = 0; r < 2; r++) {
    int i = base + r * 256;
    float y = g_A[i];
    float sc = 1e-6f + 1e-3f * fabsf(y);
    float f0 = g_K[0][0][i] + g_K[0][1][i];
    float f1 = g_K[1][0][i] + g_K[1][1][i];
    float d = (f1 - f0) / sc;
    s += d * d;
  }
  float S = blockReduce(s, sh);
  if (threadIdx.x == 0) g_red[blockIdx.x] = S;
}

__global__ __launch_bounds__(256) void k_fin1() {
  __shared__ float sh[256];
  int tid = threadIdx.x;
  float S = blockReduce(g_red[tid] + g_red[tid + 256], sh);
  if (tid == 0) {
    float h0 = g_ctl[5];
    float d2 = sqrtf(S / (float)N_ELEM) / h0;
    float d1 = g_ctl[6];
    float dmax = fmaxf(d1, d2);
    float h1 = (dmax <= 1e-15f) ? fmaxf(1e-6f, h0 * 1e-3f)
                                : powf(0.01f / dmax, 0.2f);
    g_ctl[1] = fminf(fminf(100.f * h0, h1), 1.0f);
    g_ctl[0] = 0.f;
  }
}

__global__ __launch_bounds__(256) void k_err_red() {
  if (g_done) return;
  __shared__ float sh[256];
  float hs = g_ctl[2];
  int base = blockIdx.x * 512 + threadIdx.x;
  float s = 0.f;
  #pragma unroll
  for (int r = 0; r < 2; r++) {
    int i = base + r * 256;
    float e = 0.f;
    #pragma unroll
    for (int j = 0; j < 6; j++) {
      int ki = ERR_IDX[j];
      e += ERR_C[j] * (g_K[ki][0][i] + g_K[ki][1][i]);
    }
    e *= hs;
    float y = g_A[i], yn = g_ynew[i];
    float sc = 1e-6f + 1e-3f * fmaxf(fabsf(y), fabsf(yn));
    float d = e / sc;
    s += d * d;
  }
  float S = blockReduce(s, sh);
  if (threadIdx.x == 0) g_red[blockIdx.x] = S;
}

__global__ __launch_bounds__(256) void k_finalize() {
  if (g_done) { if (threadIdx.x == 0) g_accept = 0; return; }
  __shared__ float sh[256];
  int tid = threadIdx.x;
  float S = blockReduce(g_red[tid] + g_red[tid + 256], sh);
  if (tid == 0) {
    float en = sqrtf(S / (float)N_ELEM);
    int accept = en < 1.0f;
    float safe = fmaxf(en, 1e-10f);
    float p = 0.9f * powf(safe, -0.2f);
    float fac = accept ? fminf(10.f, p) : fmaxf(0.2f, p);
    float hs = g_ctl[2];
    if (accept) g_ctl[0] = g_ctl[0] + hs;
    g_ctl[1] = hs * fac;
    g_accept = accept;
    if (g_ctl[0] >= 1.0f - 1e-7f) g_done = 1;
  }
}

__global__ __launch_bounds__(256) void k_commit() {
  if (!g_accept) return;
  int base = blockIdx.x * 512 + threadIdx.x;
  #pragma unroll
  for (int r = 0; r < 2; r++) {
    int i = base + r * 256;
    g_A[i] = g_ynew[i];
    g_K[0][0][i] = g_K[6][0][i];   // FSAL: k1 <- k7 (both splits)
    g_K[0][1][i] = g_K[6][1][i];
  }
}

// ---------------- host launcher ----------------
extern "C" void kernel_launch(void* const* d_in, const int* in_sizes, int n_in,
                              void* d_out, int out_size) {
  const float* x = (const float*)d_in[0];
  const float* P = (const float*)d_in[1];
  const float* C = (const float*)d_in[2];
  const float* F = (const float*)d_in[3];
  float* out = (float*)d_out;

  dim3 g88(8, 8);
  dim3 gNT(8, 8, 2);
  const int EB = 512, ET = 256;

  k_init_ctl<<<1, 1>>>();
  // A0 = x @ P
  k_gemm_nn<<<g88, 256>>>(x, P, nullptr, 0);
  // f0 = f(0, A0)  -> g_K[0]
  k_stage<<<EB, ET>>>(0, 0, 0, 0);
  k_gemm_nt<<<gNT, 256>>>(C, 0, 0);
  // initial step size selection
  k_red_init0<<<EB, ET>>>();
  k_fin0<<<1, 256>>>();
  k_stage<<<EB, ET>>>(1, 1, 0, 0);      // ytmp = y0 + h0*f0 at t=h0
  k_gemm_nt<<<gNT, 256>>>(C, 1, 0);     // f1 -> g_K[1]
  k_red_init1<<<EB, ET>>>();
  k_fin1<<<1, 256>>>();

  for (int s = 0; s < 20; s++) {
    k_begin<<<1, 1>>>();
    k_stage<<<EB, ET>>>(2, 1, 0, 1); k_gemm_nt<<<gNT, 256>>>(C, 1, 1);  // k2
    k_stage<<<EB, ET>>>(3, 2, 0, 1); k_gemm_nt<<<gNT, 256>>>(C, 2, 1);  // k3
    k_stage<<<EB, ET>>>(4, 3, 0, 1); k_gemm_nt<<<gNT, 256>>>(C, 3, 1);  // k4
    k_stage<<<EB, ET>>>(5, 4, 0, 1); k_gemm_nt<<<gNT, 256>>>(C, 4, 1);  // k5
    k_stage<<<EB, ET>>>(6, 5, 0, 1); k_gemm_nt<<<gNT, 256>>>(C, 5, 1);  // k6
    k_stage<<<EB, ET>>>(7, 6, 1, 1); k_gemm_nt<<<gNT, 256>>>(C, 6, 1);  // ynew + k7
    k_err_red<<<EB, ET>>>();
    k_finalize<<<1, 256>>>();
    k_commit<<<EB, ET>>>();
  }

  // y_hat = A_f @ F
  k_gemm_nn<<<g88, 256>>>(nullptr, F, out, 1);
}

// round 8
// speedup vs baseline: 1.9864x; 1.2388x over previous
#include <cuda_runtime.h>
#include <math.h>
#include <stdint.h>

#define DIM   512
#define N_ELEM (DIM*DIM)       // 262144
#define KFLAT 1024             // DT*2
#define NB    128              // persistent CTAs (all co-resident, <=148 SMs)
#define NTH   256
#define NPT   8                // elements per thread: 262144/(128*256)

// ---------------- device state ----------------
__device__ float g_A[N_ELEM];                // y
__device__ float g_K[7][2][N_ELEM];          // k1..k7, split-K partials
__device__ float g_ynew[N_ELEM];
__device__ float g_basis[N_ELEM*2];          // [b, j*2+k] interleaved sin/cos (fp32)
__device__ float g_red[2*NB];
__device__ int   g_bar_cnt;
__device__ int   g_bar_epoch;

// stage coefficient tables (Dormand-Prince)
__constant__ float STG_C[8][6] = {
  {0.f,0.f,0.f,0.f,0.f,0.f},
  {1.f,0.f,0.f,0.f,0.f,0.f},
  {0.2f,0.f,0.f,0.f,0.f,0.f},
  {3.f/40.f, 9.f/40.f, 0.f,0.f,0.f,0.f},
  {44.f/45.f, -56.f/15.f, 32.f/9.f, 0.f,0.f,0.f},
  {19372.f/6561.f, -25360.f/2187.f, 64448.f/6561.f, -212.f/729.f,0.f,0.f},
  {9017.f/3168.f, -355.f/33.f, 46732.f/5247.f, 49.f/176.f, -5103.f/18656.f, 0.f},
  {35.f/384.f, 0.f, 500.f/1113.f, 125.f/192.f, -2187.f/6784.f, 11.f/84.f},
};
__constant__ float STG_T[8] = {0.f, 1.f, 0.2f, 0.3f, 0.8f, 8.f/9.f, 1.f, 1.f};
__constant__ float ERR_C[6] = { 71.f/57600.f, -71.f/16695.f, 71.f/1920.f,
                                -17253.f/339200.f, 22.f/525.f, -1.f/40.f };
__constant__ int ERR_IDX[6] = {0, 2, 3, 4, 5, 6};

// ---------------- grid barrier (epoch-based, all CTAs resident) ----------------
__device__ __forceinline__ void gridbar(int* s_epoch) {
  __syncthreads();
  if (threadIdx.x == 0) {
    int e = ++(*s_epoch);
    __threadfence();                      // make my writes visible before arrive
    if (atomicAdd(&g_bar_cnt, 1) == NB - 1) {
      g_bar_cnt = 0;
      __threadfence();                    // count reset visible before epoch bump
      atomicExch(&g_bar_epoch, e);
    } else {
      while (*((volatile int*)&g_bar_epoch) < e) { }
    }
    __threadfence();
  }
  __syncthreads();
}

// ---------------- elementwise stage: ytmp + basis ----------------
__device__ __forceinline__ void stage_dev(int sid, int nK, int writeYnew,
                                          float hs, float t, int id) {
  float ts = t + STG_T[sid] * hs;
  int base = id * (NTH * NPT) + threadIdx.x;
  #pragma unroll
  for (int r = 0; r < NPT; r++) {
    int i = base + r * NTH;
    float y = __ldcg(&g_A[i]);
    float yt = y;
    if (nK > 0) {
      float acc = 0.f;
      for (int j = 0; j < nK; j++)
        acc += STG_C[sid][j] * (__ldcg(&g_K[j][0][i]) + __ldcg(&g_K[j][1][i]));
      yt = y + hs * acc;
    }
    if (writeYnew) g_ynew[i] = yt;
    float ph = yt + ts;        // TA=1, TB=1, TC=0
    float s, c;
    sincosf(ph, &s, &c);
    g_basis[2*i]   = s;
    g_basis[2*i+1] = c;
  }
}

// ---------------- GEMM NT device fn: g_K[dst][bz] tile = basis * C^T -------
__device__ void gemm_nt_dev(const float* __restrict__ Bm, int dstId,
                            int bx, int by, int bz,
                            float As[2][16][64], float Bs[2][16][64]) {
  float* D = &g_K[dstId][bz][0];
  int tid = threadIdx.x;
  int tx = tid & 15, ty = tid >> 4;
  int row0 = by * 64, col0 = bx * 64;
  int lr = tid >> 2;          // 0..63
  int lc = (tid & 3) * 4;     // 0,4,8,12
  int kbase = bz * 512;
  const float* Arow = &g_basis[(row0 + lr) * KFLAT + kbase + lc];
  const float* Brow = &Bm[(col0 + lr) * KFLAT + kbase + lc];

  float acc[4][4] = {};
  {
    float4 av = __ldcg((const float4*)Arow);
    float4 bv = *(const float4*)Brow;
    As[0][lc+0][lr]=av.x; As[0][lc+1][lr]=av.y; As[0][lc+2][lr]=av.z; As[0][lc+3][lr]=av.w;
    Bs[0][lc+0][lr]=bv.x; Bs[0][lc+1][lr]=bv.y; Bs[0][lc+2][lr]=bv.z; Bs[0][lc+3][lr]=bv.w;
  }
  __syncthreads();

  int cur = 0;
  for (int it = 0; it < 32; it++) {
    float4 av2, bv2;
    if (it < 31) {
      av2 = __ldcg((const float4*)(Arow + (it + 1) * 16));
      bv2 = *(const float4*)(Brow + (it + 1) * 16);
    }
    #pragma unroll
    for (int kk = 0; kk < 16; kk++) {
      float4 a = *(const float4*)&As[cur][kk][ty*4];
      float4 b = *(const float4*)&Bs[cur][kk][tx*4];
      float ar[4] = {a.x,a.y,a.z,a.w};
      float br[4] = {b.x,b.y,b.z,b.w};
      #pragma unroll
      for (int i = 0; i < 4; i++)
        #pragma unroll
        for (int j = 0; j < 4; j++)
          acc[i][j] += ar[i] * br[j];
    }
    if (it < 31) {
      int nxt = cur ^ 1;
      As[nxt][lc+0][lr]=av2.x; As[nxt][lc+1][lr]=av2.y; As[nxt][lc+2][lr]=av2.z; As[nxt][lc+3][lr]=av2.w;
      Bs[nxt][lc+0][lr]=bv2.x; Bs[nxt][lc+1][lr]=bv2.y; Bs[nxt][lc+2][lr]=bv2.z; Bs[nxt][lc+3][lr]=bv2.w;
      __syncthreads();
      cur = nxt;
    }
  }
  #pragma unroll
  for (int i = 0; i < 4; i++) {
    float4 o = {acc[i][0], acc[i][1], acc[i][2], acc[i][3]};
    *(float4*)&D[(row0 + ty*4 + i) * DIM + col0 + tx*4] = o;
  }
  __syncthreads();
}

// ---------------- block reduce ----------------
__device__ __forceinline__ float blockReduce(float v, float* sh) {
  int tid = threadIdx.x;
  sh[tid] = v; __syncthreads();
  for (int s = 128; s > 0; s >>= 1) {
    if (tid < s) sh[tid] += sh[tid + s];
    __syncthreads();
  }
  float r = sh[0];
  __syncthreads();
  return r;
}

// ordered deterministic grid sum of g_red[ofs .. ofs+NB)
__device__ __forceinline__ float gridSum(int ofs) {
  float S = 0.f;
  for (int b = 0; b < NB; b++) S += __ldcg(&g_red[ofs + b]);
  return S;
}

// ---------------- persistent ODE kernel ----------------
__global__ __launch_bounds__(NTH) void k_ode(const float* __restrict__ C) {
  __shared__ float As[2][16][64];
  __shared__ float Bs[2][16][64];
  __shared__ float sred[NTH];
  __shared__ int   s_epoch;
  int id = blockIdx.x;
  int bx = id & 7, by = (id >> 3) & 7, bz = id >> 6;
  if (threadIdx.x == 0) s_epoch = 0;
  __syncthreads();

  int base = id * (NTH * NPT) + threadIdx.x;

  // ---- f0 = f(0, A0) ----
  stage_dev(0, 0, 0, 0.f, 0.f, id);
  gridbar(&s_epoch);
  gemm_nt_dev(C, 0, bx, by, bz, As, Bs);
  gridbar(&s_epoch);

  // ---- initial step size: d0, d1 ----
  {
    float s0 = 0.f, s1 = 0.f;
    #pragma unroll
    for (int r = 0; r < NPT; r++) {
      int i = base + r * NTH;
      float y = __ldcg(&g_A[i]);
      float f = __ldcg(&g_K[0][0][i]) + __ldcg(&g_K[0][1][i]);
      float sc = 1e-6f + 1e-3f * fabsf(y);
      float a = y / sc, b = f / sc;
      s0 += a * a; s1 += b * b;
    }
    float S0 = blockReduce(s0, sred);
    float S1 = blockReduce(s1, sred);
    if (threadIdx.x == 0) { g_red[id] = S0; g_red[NB + id] = S1; }
  }
  gridbar(&s_epoch);
  float S0 = gridSum(0), S1 = gridSum(NB);
  float d0 = sqrtf(S0 / (float)N_ELEM);
  float d1 = sqrtf(S1 / (float)N_ELEM);
  float h0 = (d0 < 1e-5f || d1 < 1e-5f) ? 1e-6f : 0.01f * d0 / d1;

  // ---- f1 = f(h0, y0 + h0*f0) -> g_K[1] ----
  stage_dev(1, 1, 0, h0, 0.f, id);
  gridbar(&s_epoch);
  gemm_nt_dev(C, 1, bx, by, bz, As, Bs);
  gridbar(&s_epoch);
  {
    float s = 0.f;
    #pragma unroll
    for (int r = 0; r < NPT; r++) {
      int i = base + r * NTH;
      float y = __ldcg(&g_A[i]);
      float sc = 1e-6f + 1e-3f * fabsf(y);
      float f0 = __ldcg(&g_K[0][0][i]) + __ldcg(&g_K[0][1][i]);
      float f1 = __ldcg(&g_K[1][0][i]) + __ldcg(&g_K[1][1][i]);
      float d = (f1 - f0) / sc;
      s += d * d;
    }
    float S = blockReduce(s, sred);
    if (threadIdx.x == 0) g_red[id] = S;
  }
  gridbar(&s_epoch);
  float d2 = sqrtf(gridSum(0) / (float)N_ELEM) / h0;
  float dmax = fmaxf(d1, d2);
  float h1 = (dmax <= 1e-15f) ? fmaxf(1e-6f, h0 * 1e-3f)
                              : powf(0.01f / dmax, 0.2f);
  float h = fminf(fminf(100.f * h0, h1), 1.0f);
  float t = 0.f;

  // ---- adaptive loop (<=20 steps, uniform break when done) ----
  for (int step = 0; step < 20; step++) {
    float hs = fminf(h, 1.0f - t);

    stage_dev(2, 1, 0, hs, t, id); gridbar(&s_epoch);
    gemm_nt_dev(C, 1, bx, by, bz, As, Bs); gridbar(&s_epoch);  // k2
    stage_dev(3, 2, 0, hs, t, id); gridbar(&s_epoch);
    gemm_nt_dev(C, 2, bx, by, bz, As, Bs); gridbar(&s_epoch);  // k3
    stage_dev(4, 3, 0, hs, t, id); gridbar(&s_epoch);
    gemm_nt_dev(C, 3, bx, by, bz, As, Bs); gridbar(&s_epoch);  // k4
    stage_dev(5, 4, 0, hs, t, id); gridbar(&s_epoch);
    gemm_nt_dev(C, 4, bx, by, bz, As, Bs); gridbar(&s_epoch);  // k5
    stage_dev(6, 5, 0, hs, t, id); gridbar(&s_epoch);
    gemm_nt_dev(C, 5, bx, by, bz, As, Bs); gridbar(&s_epoch);  // k6
    stage_dev(7, 6, 1, hs, t, id); gridbar(&s_epoch);
    gemm_nt_dev(C, 6, bx, by, bz, As, Bs); gridbar(&s_epoch);  // ynew + k7

    // error norm partial
    {
      float s = 0.f;
      #pragma unroll
      for (int r = 0; r < NPT; r++) {
        int i = base + r * NTH;
        float e = 0.f;
        #pragma unroll
        for (int j = 0; j < 6; j++) {
          int ki = ERR_IDX[j];
          e += ERR_C[j] * (__ldcg(&g_K[ki][0][i]) + __ldcg(&g_K[ki][1][i]));
        }
        e *= hs;
        float y = __ldcg(&g_A[i]), yn = __ldcg(&g_ynew[i]);
        float sc = 1e-6f + 1e-3f * fmaxf(fabsf(y), fabsf(yn));
        float d = e / sc;
        s += d * d;
      }
      float S = blockReduce(s, sred);
      if (threadIdx.x == 0) g_red[id] = S;
    }
    gridbar(&s_epoch);
    float en = sqrtf(gridSum(0) / (float)N_ELEM);

    // scalar control: replicated identically in every thread
    int accept = en < 1.0f;
    float safe = fmaxf(en, 1e-10f);
    float p = 0.9f * powf(safe, -0.2f);
    float fac = accept ? fminf(10.f, p) : fmaxf(0.2f, p);
    if (accept) t = t + hs;
    h = hs * fac;

    // commit (elementwise phases share the block<->element mapping: no bar needed)
    if (accept) {
      #pragma unroll
      for (int r = 0; r < NPT; r++) {
        int i = base + r * NTH;
        g_A[i] = __ldcg(&g_ynew[i]);
        g_K[0][0][i] = __ldcg(&g_K[6][0][i]);   // FSAL
        g_K[0][1][i] = __ldcg(&g_K[6][1][i]);
      }
    }
    if (t >= 1.0f - 1e-7f) break;   // uniform across all threads/blocks
  }
}

// ---------------- barrier/state init ----------------
__global__ void k_init() { g_bar_cnt = 0; g_bar_epoch = 0; }

// ---------------- GEMM NN (SIMT fp32): mode 0: g_A = x*P ; mode 1: out = g_A*F
__global__ __launch_bounds__(256) void k_gemm_nn(const float* __restrict__ Aext,
                                                const float* __restrict__ Bm,
                                                float* outExt, int mode) {
  const float* A = mode ? g_A : Aext;
  float* D = mode ? outExt : g_A;
  const int K = DIM;
  __shared__ float As[16][64];
  __shared__ float Bs[16][64];
  int tid = threadIdx.x;
  int tx = tid & 15, ty = tid >> 4;
  int row0 = blockIdx.y * 64, col0 = blockIdx.x * 64;
  int lr = tid >> 2;
  int lc = (tid & 3) * 4;
  int br = tid >> 4;
  int bc = (tid & 15) * 4;
  float acc[4][4] = {};
  for (int k0 = 0; k0 < K; k0 += 16) {
    float4 av = *(const float4*)&A[(row0 + lr) * K + k0 + lc];
    As[lc+0][lr]=av.x; As[lc+1][lr]=av.y; As[lc+2][lr]=av.z; As[lc+3][lr]=av.w;
    float4 bv = *(const float4*)&Bm[(k0 + br) * DIM + col0 + bc];
    *(float4*)&Bs[br][bc] = bv;
    __syncthreads();
    #pragma unroll
    for (int kk = 0; kk < 16; kk++) {
      float4 a = *(const float4*)&As[kk][ty*4];
      float4 b = *(const float4*)&Bs[kk][tx*4];
      float ar[4] = {a.x,a.y,a.z,a.w};
      float br2[4] = {b.x,b.y,b.z,b.w};
      #pragma unroll
      for (int i = 0; i < 4; i++)
        #pragma unroll
        for (int j = 0; j < 4; j++)
          acc[i][j] += ar[i] * br2[j];
    }
    __syncthreads();
  }
  #pragma unroll
  for (int i = 0; i < 4; i++) {
    float4 o = {acc[i][0], acc[i][1], acc[i][2], acc[i][3]};
    *(float4*)&D[(row0 + ty*4 + i) * DIM + col0 + tx*4] = o;
  }
}

// ---------------- host launcher ----------------
extern "C" void kernel_launch(void* const* d_in, const int* in_sizes, int n_in,
                              void* d_out, int out_size) {
  const float* x = (const float*)d_in[0];
  const float* P = (const float*)d_in[1];
  const float* C = (const float*)d_in[2];
  const float* F = (const float*)d_in[3];
  float* out = (float*)d_out;

  dim3 g88(8, 8);

  k_init<<<1, 1>>>();
  k_gemm_nn<<<g88, 256>>>(x, P, nullptr, 0);     // A0 = x @ P
  k_ode<<<NB, NTH>>>(C);                         // entire RK45 integration
  k_gemm_nn<<<g88, 256>>>(nullptr, F, out, 1);   // y_hat = A_f @ F
}

// round 10
// speedup vs baseline: 2.8433x; 1.4314x over previous
#include <cuda_runtime.h>
#include <cuda_bf16.h>
#include <math.h>
#include <stdint.h>

#define DIM   512
#define N_ELEM (DIM*DIM)       // 262144
#define KFLAT 1024             // DT*2
#define NB    128              // persistent CTAs (all co-resident, <=148 SMs)
#define NTH   256
#define NPT   8                // elements per thread: 262144/(128*256)

// ---------------- device state ----------------
__device__ float g_A[N_ELEM];                // y
__device__ float g_K[7][2][N_ELEM];          // k1..k7, split-K partials
__device__ float g_ynew[N_ELEM];
__device__ __align__(16) __nv_bfloat16 g_bhi[N_ELEM*2];  // basis hi [row][j*2+k]
__device__ __align__(16) __nv_bfloat16 g_blo[N_ELEM*2];  // basis lo
__device__ __align__(16) __nv_bfloat16 g_Chi[DIM*KFLAT]; // C hi (rows = out col, K contiguous)
__device__ __align__(16) __nv_bfloat16 g_Clo[DIM*KFLAT]; // C lo
__device__ float g_red[2*NB];
__device__ int   g_bar_cnt;
__device__ int   g_bar_epoch;

// stage coefficient tables (Dormand-Prince)
__constant__ float STG_C[8][6] = {
  {0.f,0.f,0.f,0.f,0.f,0.f},
  {1.f,0.f,0.f,0.f,0.f,0.f},
  {0.2f,0.f,0.f,0.f,0.f,0.f},
  {3.f/40.f, 9.f/40.f, 0.f,0.f,0.f,0.f},
  {44.f/45.f, -56.f/15.f, 32.f/9.f, 0.f,0.f,0.f},
  {19372.f/6561.f, -25360.f/2187.f, 64448.f/6561.f, -212.f/729.f,0.f,0.f},
  {9017.f/3168.f, -355.f/33.f, 46732.f/5247.f, 49.f/176.f, -5103.f/18656.f, 0.f},
  {35.f/384.f, 0.f, 500.f/1113.f, 125.f/192.f, -2187.f/6784.f, 11.f/84.f},
};
__constant__ float STG_T[8] = {0.f, 1.f, 0.2f, 0.3f, 0.8f, 8.f/9.f, 1.f, 1.f};
__constant__ float ERR_C[6] = { 71.f/57600.f, -71.f/16695.f, 71.f/1920.f,
                                -17253.f/339200.f, 22.f/525.f, -1.f/40.f };
__constant__ int ERR_IDX[6] = {0, 2, 3, 4, 5, 6};

#define SWZ128(o) ((o) ^ (((o) >> 3) & 0x70))

__device__ __forceinline__ uint32_t smem_u32(const void* p) {
  uint32_t a;
  asm("{ .reg .u64 t; cvta.to.shared.u64 t, %1; cvt.u32.u64 %0, t; }" : "=r"(a) : "l"(p));
  return a;
}

// ---------------- grid barrier (epoch-based, all CTAs resident) ----------------
__device__ __forceinline__ void gridbar(int* s_epoch) {
  __syncthreads();
  if (threadIdx.x == 0) {
    int e = ++(*s_epoch);
    __threadfence();
    if (atomicAdd(&g_bar_cnt, 1) == NB - 1) {
      g_bar_cnt = 0;
      __threadfence();
      atomicExch(&g_bar_epoch, e);
    } else {
      while (*((volatile int*)&g_bar_epoch) < e) { }
    }
    __threadfence();
  }
  __syncthreads();
}

// ---------------- elementwise stage: ytmp + bf16 hi/lo basis ----------------
__device__ __forceinline__ void stage_dev(int sid, int nK, int writeYnew,
                                          float hs, float t, int id) {
  float ts = t + STG_T[sid] * hs;
  int base = id * (NTH * NPT) + threadIdx.x;
  #pragma unroll
  for (int r = 0; r < NPT; r++) {
    int i = base + r * NTH;
    float y = __ldcg(&g_A[i]);
    float yt = y;
    if (nK > 0) {
      float acc = 0.f;
      for (int j = 0; j < nK; j++)
        acc += STG_C[sid][j] * (__ldcg(&g_K[j][0][i]) + __ldcg(&g_K[j][1][i]));
      yt = y + hs * acc;
    }
    if (writeYnew) g_ynew[i] = yt;
    float ph = yt + ts;        // TA=1, TB=1, TC=0
    float s, c;
    sincosf(ph, &s, &c);
    __nv_bfloat16 sh = __float2bfloat16(s);
    __nv_bfloat16 ch = __float2bfloat16(c);
    float sr = s - __bfloat162float(sh);
    float cr = c - __bfloat162float(ch);
    ((__nv_bfloat162*)g_bhi)[i] = __nv_bfloat162(sh, ch);
    ((__nv_bfloat162*)g_blo)[i] = __nv_bfloat162(__float2bfloat16(sr), __float2bfloat16(cr));
  }
}

// ---------------- bf16 mma.sync GEMM NT (3-term compensated) ----------------
// g_K[dst][bz] 64x64 tile(bx,by) = sum over 24 chunks of 64:
//   seg0 Ah*Bh, seg1 Ah*Bl, seg2 Al*Bh
#define TILE_B 8192   // 64 rows x 128 bytes

__device__ __forceinline__ void mma_bf16(float* c, uint32_t a0, uint32_t a1,
                                         uint32_t a2, uint32_t a3,
                                         uint32_t b0, uint32_t b1) {
  asm volatile("mma.sync.aligned.m16n8k16.row.col.f32.bf16.bf16.f32 "
               "{%0,%1,%2,%3}, {%4,%5,%6,%7}, {%8,%9}, {%0,%1,%2,%3};"
               : "+f"(c[0]), "+f"(c[1]), "+f"(c[2]), "+f"(c[3])
               : "r"(a0), "r"(a1), "r"(a2), "r"(a3), "r"(b0), "r"(b1));
}

__device__ void gemm_nt_mma(int dstId, int bx, int by, int bz,
                            char* AsBuf, char* BsBuf) {
  float* D = &g_K[dstId][bz][0];
  int tid = threadIdx.x, wid = tid >> 5, lane = tid & 31;
  int wr = wid >> 2, wc = wid & 3;         // warp grid 2x4: tile 32x16
  int row0 = by * 64, col0 = bx * 64, kbase = bz * 512;

  // global->smem load coords: 512 x 16B chunks per operand, 2 per thread
  int c0i = tid, c1i = tid + 256;
  int lrow0 = c0i >> 3, lch0 = c0i & 7;
  int lrow1 = c1i >> 3, lch1 = c1i & 7;
  uint32_t so0 = SWZ128((uint32_t)(lrow0 * 128 + lch0 * 16));
  uint32_t so1 = SWZ128((uint32_t)(lrow1 * 128 + lch1 * 16));

  // ldmatrix lane roles
  int g = lane >> 3, r = lane & 7;
  int a_m = ((g & 1) ? 8 : 0) + r;   // reg0:(m r,k0) reg1:(m8+r,k0) reg2:(m r,k8) reg3:(m8+r,k8)
  int a_k = (g >> 1) * 8;
  int b_n = ((g >> 1) ? 8 : 0) + r;  // reg0:(n r,k0) reg1:(n r,k8) reg2:(n8+r,k0) reg3:(n8+r,k8)
  int b_k = (g & 1) * 8;

  uint32_t Asm = smem_u32(AsBuf), Bsm = smem_u32(BsBuf);

  float acc[2][2][4] = {};

  // source pointers per chunk
  auto srcA = [&](int tk) -> const __nv_bfloat16* { return (tk >> 3) == 2 ? g_blo : g_bhi; };
  auto srcB = [&](int tk) -> const __nv_bfloat16* { return (tk >> 3) == 1 ? g_Clo : g_Chi; };

  // prologue: chunk 0 -> buffer 0
  {
    const __nv_bfloat16* As = srcA(0);
    const __nv_bfloat16* Bs = srcB(0);
    int koff = kbase;
    *(uint4*)(AsBuf + so0) = __ldcg((const uint4*)&As[(row0 + lrow0) * KFLAT + koff + lch0 * 8]);
    *(uint4*)(AsBuf + so1) = __ldcg((const uint4*)&As[(row0 + lrow1) * KFLAT + koff + lch1 * 8]);
    *(uint4*)(BsBuf + so0) = __ldcg((const uint4*)&Bs[(col0 + lrow0) * KFLAT + koff + lch0 * 8]);
    *(uint4*)(BsBuf + so1) = __ldcg((const uint4*)&Bs[(col0 + lrow1) * KFLAT + koff + lch1 * 8]);
  }
  __syncthreads();

  int cur = 0;
  for (int tk = 0; tk < 24; tk++) {
    uint4 av0, av1, bv0, bv1;
    if (tk < 23) {
      const __nv_bfloat16* As = srcA(tk + 1);
      const __nv_bfloat16* Bs = srcB(tk + 1);
      int koff = kbase + ((tk + 1) & 7) * 64;
      av0 = __ldcg((const uint4*)&As[(row0 + lrow0) * KFLAT + koff + lch0 * 8]);
      av1 = __ldcg((const uint4*)&As[(row0 + lrow1) * KFLAT + koff + lch1 * 8]);
      bv0 = __ldcg((const uint4*)&Bs[(col0 + lrow0) * KFLAT + koff + lch0 * 8]);
      bv1 = __ldcg((const uint4*)&Bs[(col0 + lrow1) * KFLAT + koff + lch1 * 8]);
    }
    // compute on buffer cur
    uint32_t Ab = Asm + cur * TILE_B, Bb = Bsm + cur * TILE_B;
    #pragma unroll
    for (int s = 0; s < 4; s++) {
      uint32_t b0, b1, b2, b3;
      {
        uint32_t addr = Bb + SWZ128((uint32_t)((wc * 16 + b_n) * 128 + (s * 16 + b_k) * 2));
        asm volatile("ldmatrix.sync.aligned.m8n8.x4.shared.b16 {%0,%1,%2,%3}, [%4];"
                     : "=r"(b0), "=r"(b1), "=r"(b2), "=r"(b3) : "r"(addr));
      }
      #pragma unroll
      for (int mf = 0; mf < 2; mf++) {
        uint32_t a0, a1, a2, a3;
        uint32_t addr = Ab + SWZ128((uint32_t)((wr * 32 + mf * 16 + a_m) * 128 + (s * 16 + a_k) * 2));
        asm volatile("ldmatrix.sync.aligned.m8n8.x4.shared.b16 {%0,%1,%2,%3}, [%4];"
                     : "=r"(a0), "=r"(a1), "=r"(a2), "=r"(a3) : "r"(addr));
        mma_bf16(acc[mf][0], a0, a1, a2, a3, b0, b1);
        mma_bf16(acc[mf][1], a0, a1, a2, a3, b2, b3);
      }
    }
    if (tk < 23) {
      int nxt = cur ^ 1;
      char* Ad = AsBuf + nxt * TILE_B;
      char* Bd = BsBuf + nxt * TILE_B;
      *(uint4*)(Ad + so0) = av0;  *(uint4*)(Ad + so1) = av1;
      *(uint4*)(Bd + so0) = bv0;  *(uint4*)(Bd + so1) = bv1;
      __syncthreads();
      cur = nxt;
    }
  }

  // epilogue: write D fragments
  int mrow = row0 + wr * 32 + (lane >> 2);
  int ncol = col0 + wc * 16 + (lane & 3) * 2;
  #pragma unroll
  for (int mf = 0; mf < 2; mf++) {
    #pragma unroll
    for (int nf = 0; nf < 2; nf++) {
      float2 lo = {acc[mf][nf][0], acc[mf][nf][1]};
      float2 hi = {acc[mf][nf][2], acc[mf][nf][3]};
      *(float2*)&D[(mrow + mf * 16)     * DIM + ncol + nf * 8] = lo;
      *(float2*)&D[(mrow + mf * 16 + 8) * DIM + ncol + nf * 8] = hi;
    }
  }
  __syncthreads();
}

// ---------------- block reduce ----------------
__device__ __forceinline__ float blockReduce(float v, float* sh) {
  int tid = threadIdx.x;
  sh[tid] = v; __syncthreads();
  for (int s = 128; s > 0; s >>= 1) {
    if (tid < s) sh[tid] += sh[tid + s];
    __syncthreads();
  }
  float r = sh[0];
  __syncthreads();
  return r;
}

__device__ __forceinline__ float gridSum(int ofs) {
  float S = 0.f;
  for (int b = 0; b < NB; b++) S += __ldcg(&g_red[ofs + b]);
  return S;
}

// ---------------- persistent ODE kernel ----------------
__global__ __launch_bounds__(NTH) void k_ode() {
  __shared__ char AsBuf[2 * TILE_B];
  __shared__ char BsBuf[2 * TILE_B];
  __shared__ float sred[NTH];
  __shared__ int   s_epoch;
  int id = blockIdx.x;
  int bx = id & 7, by = (id >> 3) & 7, bz = id >> 6;
  if (threadIdx.x == 0) s_epoch = 0;
  __syncthreads();

  int base = id * (NTH * NPT) + threadIdx.x;

  // ---- f0 = f(0, A0) ----
  stage_dev(0, 0, 0, 0.f, 0.f, id);
  gridbar(&s_epoch);
  gemm_nt_mma(0, bx, by, bz, AsBuf, BsBuf);
  gridbar(&s_epoch);

  // ---- initial step size: d0, d1 ----
  {
    float s0 = 0.f, s1 = 0.f;
    #pragma unroll
    for (int r = 0; r < NPT; r++) {
      int i = base + r * NTH;
      float y = __ldcg(&g_A[i]);
      float f = __ldcg(&g_K[0][0][i]) + __ldcg(&g_K[0][1][i]);
      float sc = 1e-6f + 1e-3f * fabsf(y);
      float a = y / sc, b = f / sc;
      s0 += a * a; s1 += b * b;
    }
    float S0 = blockReduce(s0, sred);
    float S1 = blockReduce(s1, sred);
    if (threadIdx.x == 0) { g_red[id] = S0; g_red[NB + id] = S1; }
  }
  gridbar(&s_epoch);
  float S0 = gridSum(0), S1 = gridSum(NB);
  float d0 = sqrtf(S0 / (float)N_ELEM);
  float d1 = sqrtf(S1 / (float)N_ELEM);
  float h0 = (d0 < 1e-5f || d1 < 1e-5f) ? 1e-6f : 0.01f * d0 / d1;

  // ---- f1 = f(h0, y0 + h0*f0) -> g_K[1] ----
  stage_dev(1, 1, 0, h0, 0.f, id);
  gridbar(&s_epoch);
  gemm_nt_mma(1, bx, by, bz, AsBuf, BsBuf);
  gridbar(&s_epoch);
  {
    float s = 0.f;
    #pragma unroll
    for (int r = 0; r < NPT; r++) {
      int i = base + r * NTH;
      float y = __ldcg(&g_A[i]);
      float sc = 1e-6f + 1e-3f * fabsf(y);
      float f0 = __ldcg(&g_K[0][0][i]) + __ldcg(&g_K[0][1][i]);
      float f1 = __ldcg(&g_K[1][0][i]) + __ldcg(&g_K[1][1][i]);
      float d = (f1 - f0) / sc;
      s += d * d;
    }
    float S = blockReduce(s, sred);
    if (threadIdx.x == 0) g_red[id] = S;
  }
  gridbar(&s_epoch);
  float d2 = sqrtf(gridSum(0) / (float)N_ELEM) / h0;
  float dmax = fmaxf(d1, d2);
  float h1 = (dmax <= 1e-15f) ? fmaxf(1e-6f, h0 * 1e-3f)
                              : powf(0.01f / dmax, 0.2f);
  float h = fminf(fminf(100.f * h0, h1), 1.0f);
  float t = 0.f;

  // ---- adaptive loop (<=20 steps, uniform break when done) ----
  for (int step = 0; step < 20; step++) {
    float hs = fminf(h, 1.0f - t);

    stage_dev(2, 1, 0, hs, t, id); gridbar(&s_epoch);
    gemm_nt_mma(1, bx, by, bz, AsBuf, BsBuf); gridbar(&s_epoch);  // k2
    stage_dev(3, 2, 0, hs, t, id); gridbar(&s_epoch);
    gemm_nt_mma(2, bx, by, bz, AsBuf, BsBuf); gridbar(&s_epoch);  // k3
    stage_dev(4, 3, 0, hs, t, id); gridbar(&s_epoch);
    gemm_nt_mma(3, bx, by, bz, AsBuf, BsBuf); gridbar(&s_epoch);  // k4
    stage_dev(5, 4, 0, hs, t, id); gridbar(&s_epoch);
    gemm_nt_mma(4, bx, by, bz, AsBuf, BsBuf); gridbar(&s_epoch);  // k5
    stage_dev(6, 5, 0, hs, t, id); gridbar(&s_epoch);
    gemm_nt_mma(5, bx, by, bz, AsBuf, BsBuf); gridbar(&s_epoch);  // k6
    stage_dev(7, 6, 1, hs, t, id); gridbar(&s_epoch);
    gemm_nt_mma(6, bx, by, bz, AsBuf, BsBuf); gridbar(&s_epoch);  // ynew + k7

    // error norm partial
    {
      float s = 0.f;
      #pragma unroll
      for (int r = 0; r < NPT; r++) {
        int i = base + r * NTH;
        float e = 0.f;
        #pragma unroll
        for (int j = 0; j < 6; j++) {
          int ki = ERR_IDX[j];
          e += ERR_C[j] * (__ldcg(&g_K[ki][0][i]) + __ldcg(&g_K[ki][1][i]));
        }
        e *= hs;
        float y = __ldcg(&g_A[i]), yn = __ldcg(&g_ynew[i]);
        float sc = 1e-6f + 1e-3f * fmaxf(fabsf(y), fabsf(yn));
        float d = e / sc;
        s += d * d;
      }
      float S = blockReduce(s, sred);
      if (threadIdx.x == 0) g_red[id] = S;
    }
    gridbar(&s_epoch);
    float en = sqrtf(gridSum(0) / (float)N_ELEM);

    int accept = en < 1.0f;
    float safe = fmaxf(en, 1e-10f);
    float p = 0.9f * powf(safe, -0.2f);
    float fac = accept ? fminf(10.f, p) : fmaxf(0.2f, p);
    if (accept) t = t + hs;
    h = hs * fac;

    if (accept) {
      #pragma unroll
      for (int r = 0; r < NPT; r++) {
        int i = base + r * NTH;
        g_A[i] = __ldcg(&g_ynew[i]);
        g_K[0][0][i] = __ldcg(&g_K[6][0][i]);   // FSAL
        g_K[0][1][i] = __ldcg(&g_K[6][1][i]);
      }
    }
    if (t >= 1.0f - 1e-7f) break;
  }
}

// ---------------- barrier/state init ----------------
__global__ void k_init() { g_bar_cnt = 0; g_bar_epoch = 0; }

// ---------------- C hi/lo split (once per launch) ----------------
__global__ __launch_bounds__(256) void k_prep_C(const float* __restrict__ C) {
  int base = blockIdx.x * 1024 + threadIdx.x;
  #pragma unroll
  for (int r = 0; r < 4; r++) {
    int i = base + r * 256;
    float v = C[i];
    __nv_bfloat16 h = __float2bfloat16(v);
    g_Chi[i] = h;
    g_Clo[i] = __float2bfloat16(v - __bfloat162float(h));
  }
}

// ---------------- GEMM NN (SIMT fp32): mode 0: g_A = x*P ; mode 1: out = g_A*F
__global__ __launch_bounds__(256) void k_gemm_nn(const float* __restrict__ Aext,
                                                const float* __restrict__ Bm,
                                                float* outExt, int mode) {
  const float* A = mode ? g_A : Aext;
  float* D = mode ? outExt : g_A;
  const int K = DIM;
  __shared__ float As[16][64];
  __shared__ float Bs[16][64];
  int tid = threadIdx.x;
  int tx = tid & 15, ty = tid >> 4;
  int row0 = blockIdx.y * 64, col0 = blockIdx.x * 64;
  int lr = tid >> 2;
  int lc = (tid & 3) * 4;
  int br = tid >> 4;
  int bc = (tid & 15) * 4;
  float acc[4][4] = {};
  for (int k0 = 0; k0 < K; k0 += 16) {
    float4 av = *(const float4*)&A[(row0 + lr) * K + k0 + lc];
    As[lc+0][lr]=av.x; As[lc+1][lr]=av.y; As[lc+2][lr]=av.z; As[lc+3][lr]=av.w;
    float4 bv = *(const float4*)&Bm[(k0 + br) * DIM + col0 + bc];
    *(float4*)&Bs[br][bc] = bv;
    __syncthreads();
    #pragma unroll
    for (int kk = 0; kk < 16; kk++) {
      float4 a = *(const float4*)&As[kk][ty*4];
      float4 b = *(const float4*)&Bs[kk][tx*4];
      float ar[4] = {a.x,a.y,a.z,a.w};
      float br2[4] = {b.x,b.y,b.z,b.w};
      #pragma unroll
      for (int i = 0; i < 4; i++)
        #pragma unroll
        for (int j = 0; j < 4; j++)
          acc[i][j] += ar[i] * br2[j];
    }
    __syncthreads();
  }
  #pragma unroll
  for (int i = 0; i < 4; i++) {
    float4 o = {acc[i][0], acc[i][1], acc[i][2], acc[i][3]};
    *(float4*)&D[(row0 + ty*4 + i) * DIM + col0 + tx*4] = o;
  }
}

// ---------------- host launcher ----------------
extern "C" void kernel_launch(void* const* d_in, const int* in_sizes, int n_in,
                              void* d_out, int out_size) {
  const float* x = (const float*)d_in[0];
  const float* P = (const float*)d_in[1];
  const float* C = (const float*)d_in[2];
  const float* F = (const float*)d_in[3];
  float* out = (float*)d_out;

  dim3 g88(8, 8);

  k_init<<<1, 1>>>();
  k_prep_C<<<512, 256>>>(C);
  k_gemm_nn<<<g88, 256>>>(x, P, nullptr, 0);     // A0 = x @ P
  k_ode<<<NB, NTH>>>();                          // entire RK45 integration
  k_gemm_nn<<<g88, 256>>>(nullptr, F, out, 1);   // y_hat = A_f @ F
}